// round 10
// baseline (speedup 1.0000x reference)
#include <cuda_runtime.h>
#include <cstddef>

// ---------------------------------------------------------------------------
// learn_wavelet: 3-level learnable lifting wavelet.
// Subnets: packed f32x2 FMA; hidden tensor in SMEM as fp32 channel-pairs,
// now 2 pairs / position (16B) over 4 passes => sH halves to 38KB so 3 blocks
// fit per SM (occ 23.7% -> ~35%). Stage-1 computes 2 adjacent hidden positions
// per thread (LDS.128 taps). Stage-2: 2x4 px/thread; one 16B load per hidden
// position now carries both active pairs, so total stage-2 loads unchanged.
// Swizzle identity swz(x+16)==swz(x)^16 used only where x%32==0.
// ---------------------------------------------------------------------------

#define NIMG 24
typedef unsigned long long ull;

// Scratch (device globals: allocation-free per harness rules)
__device__ float g_L [NIMG * 256 * 512];
__device__ float g_H [NIMG * 256 * 512];
__device__ float g_LL[NIMG * 256 * 256];
__device__ float g_HL[NIMG * 256 * 256];
__device__ float g_LH[NIMG * 256 * 256];
__device__ float g_HH[NIMG * 256 * 256];

// Channel-paired weights: pair p holds (ch 2p, ch 2p+1) in (lo, hi).
struct PackedW {
    ull   w1[2][8][9];   // [pset][pair][tap]
    ull   b1[2][8];
    ull   w2[2][8][9];
    float b2[2];
    float pad[2];
};
__device__   PackedW g_pack;
__constant__ PackedW c_pack;

// ---------------- packed f32x2 helpers ----------------
__device__ __forceinline__ ull fma2(ull a, ull b, ull c) {
    ull d; asm("fma.rn.f32x2 %0, %1, %2, %3;" : "=l"(d) : "l"(a), "l"(b), "l"(c));
    return d;
}
__device__ __forceinline__ ull pack2(float lo, float hi) {
    ull d;
    asm("mov.b64 %0, {%1, %2};" : "=l"(d)
        : "r"(__float_as_uint(lo)), "r"(__float_as_uint(hi)));
    return d;
}
__device__ __forceinline__ float2 unpack2(ull a) {
    unsigned lo, hi;
    asm("mov.b64 {%0, %1}, %2;" : "=r"(lo), "=r"(hi) : "l"(a));
    return make_float2(__uint_as_float(lo), __uint_as_float(hi));
}

// XOR swizzle: bits[7:9] -> bits[4:6].
__device__ __forceinline__ unsigned swz(unsigned b) {
    return b ^ ((b >> 3) & 0x70);
}

// SMEM partition (dynamic): sH (66*36*16 = 38016B) then sIn (68*36*8 = 19584B)
#define SH_BYTES   (66 * 36 * 16)
#define SMEM_TOTAL (SH_BYTES + 68 * 36 * 8)

// ---------------------------------------------------------------------------
// Prep kernel: pack channel-paired weights into g_pack (then memcpy to const).
// ---------------------------------------------------------------------------
__global__ void prep_kernel(const float* __restrict__ Wp1, const float* __restrict__ bp1,
                            const float* __restrict__ Wp2, const float* __restrict__ bp2,
                            const float* __restrict__ Wu1, const float* __restrict__ bu1,
                            const float* __restrict__ Wu2, const float* __restrict__ bu2)
{
    int t = threadIdx.x;
    const float* W1s[2] = {Wp1, Wu1};
    const float* B1s[2] = {bp1, bu1};
    const float* W2s[2] = {Wp2, Wu2};
    const float* B2s[2] = {bp2, bu2};
    if (t < 144) {
        int ps = t / 72, r = t - ps * 72, p = r / 9, k = r - p * 9;
        *(float2*)&g_pack.w1[ps][p][k] =
            make_float2(W1s[ps][(2 * p) * 9 + k], W1s[ps][(2 * p + 1) * 9 + k]);
        *(float2*)&g_pack.w2[ps][p][k] =
            make_float2(W2s[ps][(2 * p) * 9 + k], W2s[ps][(2 * p + 1) * 9 + k]);
    }
    if (t < 16) {
        int ps = t / 8, p = t - ps * 8;
        *(float2*)&g_pack.b1[ps][p] = make_float2(B1s[ps][2 * p], B1s[ps][2 * p + 1]);
    }
    if (t < 2) g_pack.b2[t] = B2s[t][0];
}

// ---------------------------------------------------------------------------
// Kernel 1: RGB->YUV + even/odd row split.
// ---------------------------------------------------------------------------
__global__ void yuv_split_kernel(const float* __restrict__ x,
                                 float* __restrict__ L, float* __restrict__ H)
{
    int b   = blockIdx.y;
    int idx = blockIdx.x * 256 + threadIdx.x;
    int y   = idx >> 9;
    int xx  = idx & 511;

    const float* xb = x + (size_t)b * 3 * 262144;
    float r  = xb[idx];
    float g  = xb[262144 + idx];
    float bl = xb[2 * 262144 + idx];

    float Y =  0.299f * r + 0.587f * g + 0.114f * bl;
    float U = -0.147f * r - 0.289f * g + 0.436f * bl;
    float V =  0.615f * r - 0.515f * g - 0.100f * bl;

    float* dst = (y & 1) ? H : L;
    size_t o = (size_t)(y >> 1) * 512 + xx;
    const size_t istr = (size_t)256 * 512;
    dst[(size_t)(0 * 8 + b) * istr + o] = Y;
    dst[(size_t)(1 * 8 + b) * istr + o] = U;
    dst[(size_t)(2 * 8 + b) * istr + o] = V;
}

// ---------------------------------------------------------------------------
// Stage-1 helper: conv 1->4 (pairs 2p, 2p+1) + relu for TWO adjacent hidden
// positions per thread. Taps via LDS.128 of duplicated float2 input.
// Each position stores ONE float4 (2 pairs, 16B). CHK=false for interior.
// ---------------------------------------------------------------------------
template <bool CHK>
__device__ __forceinline__ void stage1(const float2* sIn, char* sHb,
                                       int pset, int p, int by, int bx,
                                       int h, int w, int tid)
{
    // 66 rows x 17 column pairs (hx = 0,2,...,32)
    for (int idx = tid; idx < 66 * 17; idx += 256) {
        int hy = idx / 17, hp = idx - hy * 17;
        int hx = hp * 2;

        ull b0 = c_pack.b1[pset][2 * p + 0];
        ull b1 = c_pack.b1[pset][2 * p + 1];
        ull cA0 = b0, cA1 = b1;   // pos hx
        ull cB0 = b0, cB1 = b1;   // pos hx+1

#pragma unroll
        for (int dy = 0; dy < 3; dy++) {
            const ull* row = (const ull*)&sIn[(hy + dy) * 36 + hx];
            ulonglong2 ta = *(const ulonglong2*)row;        // taps hx, hx+1
            ulonglong2 tb = *(const ulonglong2*)(row + 2);  // taps hx+2, hx+3
            ull t0 = ta.x, t1 = ta.y, t2 = tb.x, t3 = tb.y;

            ull w0 = c_pack.w1[pset][2 * p + 0][dy * 3 + 0];
            ull w1 = c_pack.w1[pset][2 * p + 0][dy * 3 + 1];
            ull w2 = c_pack.w1[pset][2 * p + 0][dy * 3 + 2];
            cA0 = fma2(w0, t0, cA0); cB0 = fma2(w0, t1, cB0);
            cA0 = fma2(w1, t1, cA0); cB0 = fma2(w1, t2, cB0);
            cA0 = fma2(w2, t2, cA0); cB0 = fma2(w2, t3, cB0);

            ull u0 = c_pack.w1[pset][2 * p + 1][dy * 3 + 0];
            ull u1 = c_pack.w1[pset][2 * p + 1][dy * 3 + 1];
            ull u2 = c_pack.w1[pset][2 * p + 1][dy * 3 + 2];
            cA1 = fma2(u0, t0, cA1); cB1 = fma2(u0, t1, cB1);
            cA1 = fma2(u1, t1, cA1); cB1 = fma2(u1, t2, cB1);
            cA1 = fma2(u2, t2, cA1); cB1 = fma2(u2, t3, cB1);
        }

        bool validA = true, validB = true;
        if (CHK) {
            int gy = by + hy - 1, gx = bx + hx - 1;
            bool vy = (gy >= 0 && gy < h);
            validA = vy && (gx >= 0 && gx < w);
            validB = vy && (gx + 1 >= 0 && gx + 1 < w);
        }

        {   // pos hx : one float4 = pairs 2p, 2p+1
            float2 f0 = unpack2(cA0), f1 = unpack2(cA1);
            float4 v;
            v.x = validA ? fmaxf(f0.x, 0.f) : 0.f;
            v.y = validA ? fmaxf(f0.y, 0.f) : 0.f;
            v.z = validA ? fmaxf(f1.x, 0.f) : 0.f;
            v.w = validA ? fmaxf(f1.y, 0.f) : 0.f;
            unsigned a0 = swz((unsigned)(hy * 36 + hx) * 16);
            *(float4*)(sHb + a0) = v;
            // pos hx+1 : base%32==0 so swz(base+16) == swz(base)^16
            float2 g0 = unpack2(cB0), g1 = unpack2(cB1);
            float4 u;
            u.x = validB ? fmaxf(g0.x, 0.f) : 0.f;
            u.y = validB ? fmaxf(g0.y, 0.f) : 0.f;
            u.z = validB ? fmaxf(g1.x, 0.f) : 0.f;
            u.w = validB ? fmaxf(g1.y, 0.f) : 0.f;
            *(float4*)(sHb + (a0 ^ 16)) = u;
        }
    }
}

// ---------------------------------------------------------------------------
// Kernel 2: fused subnet + lift.  O[p] = S[p] + sign*subnet(I)[p]
// Tile 32w x 64h, 256 threads, 4 passes of 4 channels (2 pairs, 16B/pos).
// grid.z in [0, 2*NIMG): z < NIMG uses buffer set A, else set B.
// __launch_bounds__(256,3): reg budget 85, 3 blocks/SM (57.6KB SMEM each).
// SAME padding of conv2 zero-pads the *hidden* tensor (off-image hidden = 0).
// ---------------------------------------------------------------------------
__global__ void __launch_bounds__(256, 3)
subnet_lift_kernel(const float* __restrict__ IA, const float* __restrict__ SA,
                   float* __restrict__ OA,
                   const float* __restrict__ IB, const float* __restrict__ SB,
                   float* __restrict__ OB,
                   int pset, float sign, int h, int w)
{
    extern __shared__ char dynsmem[];
    char*   sHb = dynsmem;                          // 66*36 pos * 16B
    float2* sIn = (float2*)(dynsmem + SH_BYTES);    // 68 rows * 36 cols, dup'd

    const int tid = threadIdx.x;
    int z = blockIdx.z;
    const int setB = (z >= NIMG);
    const int img  = setB ? z - NIMG : z;
    const float* I = setB ? IB : IA;
    const float* S = setB ? SB : SA;
    float*       O = setB ? OB : OA;

    const int bx = blockIdx.x * 32;
    const int by = blockIdx.y * 64;
    const float* Ii = I + (size_t)img * h * w;

    const bool interior = (bx >= 2) && (bx + 34 <= w) &&
                          (by >= 2) && (by + 66 <= h);

    // --- load input tile (rows by-2..by+65, cols bx-2..bx+33), duplicated ---
    if (interior) {
        for (int idx = tid; idx < 68 * 36; idx += 256) {
            int ly = idx / 36, lx = idx - ly * 36;
            float v = Ii[(size_t)(by + ly - 2) * w + (bx + lx - 2)];
            sIn[idx] = make_float2(v, v);
        }
    } else {
        for (int idx = tid; idx < 68 * 36; idx += 256) {
            int ly = idx / 36, lx = idx - ly * 36;
            int gy = by + ly - 2, gx = bx + lx - 2;
            float v = 0.f;
            if (gy >= 0 && gy < h && gx >= 0 && gx < w)
                v = Ii[(size_t)gy * w + gx];
            sIn[idx] = make_float2(v, v);
        }
    }
    __syncthreads();

    // stage-2 ownership: rows 2r, 2r+1; cols oxq..oxq+3
    const int r   = tid >> 3;            // 0..31
    const int oxq = (tid & 7) * 4;       // 0,4,...,28

    const ull bias2 = pack2(c_pack.b2[pset], 0.f);  // bias once per px (lo)
    ull a00 = bias2, a01 = bias2, a02 = bias2, a03 = bias2;  // row 2r
    ull a10 = bias2, a11 = bias2, a12 = bias2, a13 = bias2;  // row 2r+1

#pragma unroll 1
    for (int p = 0; p < 4; p++) {        // pass p: pairs 2p, 2p+1
        if (interior)
            stage1<false>(sIn, sHb, pset, p, by, bx, h, w, tid);
        else
            stage1<true>(sIn, sHb, pset, p, by, bx, h, w, tid);
        __syncthreads();

        const ull* wA = c_pack.w2[pset][2 * p];
        const ull* wB = wA + 9;          // next pair, contiguous

        // --- stage 2 partial: conv 4->1, 2 output rows sharing hidden rows ---
#pragma unroll
        for (int hr = 0; hr < 4; hr++) {
            const int hy = 2 * r + hr;
            unsigned base = (unsigned)(hy * 36 + oxq) * 16;

            ull A[6], B[6];
#pragma unroll
            for (int j = 0; j < 6; j++) {
                ulonglong2 v =
                    *(const ulonglong2*)(sHb + swz(base + j * 16));
                A[j] = v.x; B[j] = v.y;
            }
            if (hr <= 2) {            // contributes to row 2r (dy = hr)
#pragma unroll
                for (int t = 0; t < 3; t++) {
                    ull wa = wA[hr * 3 + t], wb = wB[hr * 3 + t];
                    a00 = fma2(wa, A[t],     a00);
                    a01 = fma2(wa, A[t + 1], a01);
                    a02 = fma2(wa, A[t + 2], a02);
                    a03 = fma2(wa, A[t + 3], a03);
                    a00 = fma2(wb, B[t],     a00);
                    a01 = fma2(wb, B[t + 1], a01);
                    a02 = fma2(wb, B[t + 2], a02);
                    a03 = fma2(wb, B[t + 3], a03);
                }
            }
            if (hr >= 1) {            // contributes to row 2r+1 (dy = hr-1)
#pragma unroll
                for (int t = 0; t < 3; t++) {
                    ull wa = wA[(hr - 1) * 3 + t], wb = wB[(hr - 1) * 3 + t];
                    a10 = fma2(wa, A[t],     a10);
                    a11 = fma2(wa, A[t + 1], a11);
                    a12 = fma2(wa, A[t + 2], a12);
                    a13 = fma2(wa, A[t + 3], a13);
                    a10 = fma2(wb, B[t],     a10);
                    a11 = fma2(wb, B[t + 1], a11);
                    a12 = fma2(wb, B[t + 2], a12);
                    a13 = fma2(wb, B[t + 3], a13);
                }
            }
        }
        if (p < 3) __syncthreads();   // before next pass overwrites sH
    }

    // --- epilogue: O = S + sign*acc, float4 per row ---
    float2 f00 = unpack2(a00), f01 = unpack2(a01),
           f02 = unpack2(a02), f03 = unpack2(a03);
    float2 f10 = unpack2(a10), f11 = unpack2(a11),
           f12 = unpack2(a12), f13 = unpack2(a13);

    const float* Si = S + (size_t)img * h * w;
    float* Oi = O + (size_t)img * h * w;
    size_t p0 = (size_t)(by + 2 * r) * w + bx + oxq;
    size_t p1 = p0 + w;

    float4 s0 = *(const float4*)(Si + p0);
    float4 s1 = *(const float4*)(Si + p1);
    float4 o0, o1;
    o0.x = s0.x + sign * (f00.x + f00.y);
    o0.y = s0.y + sign * (f01.x + f01.y);
    o0.z = s0.z + sign * (f02.x + f02.y);
    o0.w = s0.w + sign * (f03.x + f03.y);
    o1.x = s1.x + sign * (f10.x + f10.y);
    o1.y = s1.y + sign * (f11.x + f11.y);
    o1.z = s1.z + sign * (f12.x + f12.y);
    o1.w = s1.w + sign * (f13.x + f13.y);
    *(float4*)(Oi + p0) = o0;
    *(float4*)(Oi + p1) = o1;
}

// ---------------------------------------------------------------------------
// Kernel 3: transpose + even/odd split (L and H via grid.z).
// ---------------------------------------------------------------------------
__global__ void transpose_split_kernel(const float* __restrict__ Lsrc,
                                       const float* __restrict__ Hsrc,
                                       float* __restrict__ LLd, float* __restrict__ HLd,
                                       float* __restrict__ LHd, float* __restrict__ HHd,
                                       int h, int w)
{
    __shared__ float tile[32][65];
    int z = blockIdx.z;
    int which = z / NIMG, img = z - which * NIMG;
    const float* T = which ? Hsrc : Lsrc;
    float* E = which ? LHd : LLd;
    float* O = which ? HHd : HLd;

    const int c0 = blockIdx.x * 32;
    const int r0 = blockIdx.y * 32;
    const int tx = threadIdx.x, ty = threadIdx.y;

    const float* Ti = T + (size_t)img * h * w;
#pragma unroll
    for (int k = 0; k < 4; k++) {
        int cc = ty + 8 * k;
        const float* row = Ti + (size_t)(c0 + cc) * w + 2 * r0;
        tile[cc][tx]      = row[tx];
        tile[cc][tx + 32] = row[tx + 32];
    }
    __syncthreads();

    size_t imgo = (size_t)img * (w / 2) * h;
#pragma unroll
    for (int k = 0; k < 4; k++) {
        int rr = ty + 8 * k;
        size_t o = imgo + (size_t)(r0 + rr) * h + c0 + tx;
        E[o] = tile[tx][2 * rr];
        O[o] = tile[tx][2 * rr + 1];
    }
}

// ---------------------------------------------------------------------------
// Kernel 4: gather. out[b, q*3+c, i, j] = Q_q[c*8+b, j, i]
// ---------------------------------------------------------------------------
__global__ void gather_kernel(const float* __restrict__ LL, const float* __restrict__ HL,
                              const float* __restrict__ LH, const float* __restrict__ HH,
                              float* __restrict__ out)
{
    __shared__ float tile[32][33];
    int z = blockIdx.z;
    int q = z / NIMG, img = z - q * NIMG;
    const float* Q = (q == 0) ? LL : (q == 1) ? HL : (q == 2) ? LH : HH;
    int b = img & 7, cch = img >> 3;
    int chan = q * 3 + cch;

    int i0 = blockIdx.x * 32, j0 = blockIdx.y * 32;
    int tx = threadIdx.x, ty = threadIdx.y;

    const float* Qi = Q + (size_t)img * 65536;
#pragma unroll
    for (int k = 0; k < 4; k++) {
        int jj = ty + 8 * k;
        tile[jj][tx] = Qi[(size_t)(j0 + jj) * 256 + i0 + tx];
    }
    __syncthreads();

    float* o = out + ((size_t)b * 12 + chan) * 65536;
#pragma unroll
    for (int k = 0; k < 4; k++) {
        int ii = ty + 8 * k;
        o[(size_t)(i0 + ii) * 256 + j0 + tx] = tile[tx][ii];
    }
}

// ---------------------------------------------------------------------------
extern "C" void kernel_launch(void* const* d_in, const int* in_sizes, int n_in,
                              void* d_out, int out_size)
{
    const float* x   = (const float*)d_in[0];
    const float* Wp1 = (const float*)d_in[1];
    const float* bp1 = (const float*)d_in[2];
    const float* Wp2 = (const float*)d_in[3];
    const float* bp2 = (const float*)d_in[4];
    const float* Wu1 = (const float*)d_in[5];
    const float* bu1 = (const float*)d_in[6];
    const float* Wu2 = (const float*)d_in[7];
    const float* bu2 = (const float*)d_in[8];
    float* out = (float*)d_out;

    // opt in to >48KB dynamic SMEM (idempotent)
    cudaFuncSetAttribute(subnet_lift_kernel,
                         cudaFuncAttributeMaxDynamicSharedMemorySize, SMEM_TOTAL);

    // pack weights on device, then stage into __constant__
    prep_kernel<<<1, 256>>>(Wp1, bp1, Wp2, bp2, Wu1, bu1, Wu2, bu2);
    PackedW* pg;
    cudaGetSymbolAddress((void**)&pg, g_pack);
    cudaMemcpyToSymbolAsync(c_pack, pg, sizeof(PackedW), 0, cudaMemcpyDeviceToDevice);

    float *pL, *pH, *pLL, *pHL, *pLH, *pHH;
    cudaGetSymbolAddress((void**)&pL,  g_L);
    cudaGetSymbolAddress((void**)&pH,  g_H);
    cudaGetSymbolAddress((void**)&pLL, g_LL);
    cudaGetSymbolAddress((void**)&pHL, g_HL);
    cudaGetSymbolAddress((void**)&pLH, g_LH);
    cudaGetSymbolAddress((void**)&pHH, g_HH);

    // 1) rgb->yuv + row split
    yuv_split_kernel<<<dim3(1024, 8), 256>>>(x, pL, pH);

    // 2) lift 1 (rows), 24 x 256 x 512 ; tiles 32w x 64h
    dim3 g1(512 / 32, 256 / 64, NIMG);
    subnet_lift_kernel<<<g1, 256, SMEM_TOTAL>>>(pL, pH, pH, pL, pH, pH,
                                                0, -1.f, 256, 512);
    subnet_lift_kernel<<<g1, 256, SMEM_TOTAL>>>(pH, pL, pL, pH, pL, pL,
                                                1, +1.f, 256, 512);

    // 3) transpose + column split
    dim3 gt(256 / 32, 256 / 32, 2 * NIMG);
    transpose_split_kernel<<<gt, dim3(32, 8)>>>(pL, pH, pLL, pHL, pLH, pHH, 256, 512);

    // 4) lift 2 (L branch) and lift 3 (H branch) fused per step, grid.z = 48
    dim3 g2(256 / 32, 256 / 64, 2 * NIMG);
    subnet_lift_kernel<<<g2, 256, SMEM_TOTAL>>>(pLL, pHL, pHL, pLH, pHH, pHH,
                                                0, -1.f, 256, 256);
    subnet_lift_kernel<<<g2, 256, SMEM_TOTAL>>>(pHL, pLL, pLL, pHH, pLH, pLH,
                                                1, +1.f, 256, 256);

    // 5) transpose back + batch2channel + concat -> out [8,12,256,256]
    gather_kernel<<<dim3(8, 8, 96), dim3(32, 8)>>>(pLL, pHL, pLH, pHH, out);
}

// round 12
// speedup vs baseline: 1.1001x; 1.1001x over previous
#include <cuda_runtime.h>
#include <cstddef>

// ---------------------------------------------------------------------------
// learn_wavelet: 3-level learnable lifting wavelet.
// Subnets: packed f32x2 FMA; hidden in SMEM as fp32 channel-pairs, 4 pairs per
// position (32B), XOR-swizzled, 2 passes of 8 channels (R9 structure — the
// 4-pass variant regressed: crossbar-bound). Stage-1: 2x2 position quad per
// thread (tap rows shared, 8 LDS.128 / 4 pos). Stage-2: 2x4 px/thread with
// all 12 position-loads batched ahead of the FMA block.
// Swizzle identity swz(x+16)==swz(x)^16 holds only for x % 32 == 0.
// ---------------------------------------------------------------------------

#define NIMG 24
typedef unsigned long long ull;

// Scratch (device globals: allocation-free per harness rules)
__device__ float g_L [NIMG * 256 * 512];
__device__ float g_H [NIMG * 256 * 512];
__device__ float g_LL[NIMG * 256 * 256];
__device__ float g_HL[NIMG * 256 * 256];
__device__ float g_LH[NIMG * 256 * 256];
__device__ float g_HH[NIMG * 256 * 256];

// Channel-paired weights: pair p holds (ch 2p, ch 2p+1) in (lo, hi).
struct PackedW {
    ull   w1[2][8][9];   // [pset][pair][tap]
    ull   b1[2][8];
    ull   w2[2][8][9];
    float b2[2];
    float pad[2];
};
__device__   PackedW g_pack;
__constant__ PackedW c_pack;

// ---------------- packed f32x2 helpers ----------------
__device__ __forceinline__ ull fma2(ull a, ull b, ull c) {
    ull d; asm("fma.rn.f32x2 %0, %1, %2, %3;" : "=l"(d) : "l"(a), "l"(b), "l"(c));
    return d;
}
__device__ __forceinline__ ull pack2(float lo, float hi) {
    ull d;
    asm("mov.b64 %0, {%1, %2};" : "=l"(d)
        : "r"(__float_as_uint(lo)), "r"(__float_as_uint(hi)));
    return d;
}
__device__ __forceinline__ float2 unpack2(ull a) {
    unsigned lo, hi;
    asm("mov.b64 {%0, %1}, %2;" : "=r"(lo), "=r"(hi) : "l"(a));
    return make_float2(__uint_as_float(lo), __uint_as_float(hi));
}

// XOR swizzle: bits[7:9] -> bits[4:6].
__device__ __forceinline__ unsigned swz(unsigned b) {
    return b ^ ((b >> 3) & 0x70);
}

// SMEM partition (dynamic): sH (66*36*32 = 76032B) then sIn (68*36*8 = 19584B)
#define SH_BYTES   (66 * 36 * 32)
#define SMEM_TOTAL (SH_BYTES + 68 * 36 * 8)

// ---------------------------------------------------------------------------
// Prep kernel: pack channel-paired weights into g_pack (then memcpy to const).
// ---------------------------------------------------------------------------
__global__ void prep_kernel(const float* __restrict__ Wp1, const float* __restrict__ bp1,
                            const float* __restrict__ Wp2, const float* __restrict__ bp2,
                            const float* __restrict__ Wu1, const float* __restrict__ bu1,
                            const float* __restrict__ Wu2, const float* __restrict__ bu2)
{
    int t = threadIdx.x;
    const float* W1s[2] = {Wp1, Wu1};
    const float* B1s[2] = {bp1, bu1};
    const float* W2s[2] = {Wp2, Wu2};
    const float* B2s[2] = {bp2, bu2};
    if (t < 144) {
        int ps = t / 72, r = t - ps * 72, p = r / 9, k = r - p * 9;
        *(float2*)&g_pack.w1[ps][p][k] =
            make_float2(W1s[ps][(2 * p) * 9 + k], W1s[ps][(2 * p + 1) * 9 + k]);
        *(float2*)&g_pack.w2[ps][p][k] =
            make_float2(W2s[ps][(2 * p) * 9 + k], W2s[ps][(2 * p + 1) * 9 + k]);
    }
    if (t < 16) {
        int ps = t / 8, p = t - ps * 8;
        *(float2*)&g_pack.b1[ps][p] = make_float2(B1s[ps][2 * p], B1s[ps][2 * p + 1]);
    }
    if (t < 2) g_pack.b2[t] = B2s[t][0];
}

// ---------------------------------------------------------------------------
// Kernel 1: RGB->YUV + even/odd row split.
// ---------------------------------------------------------------------------
__global__ void yuv_split_kernel(const float* __restrict__ x,
                                 float* __restrict__ L, float* __restrict__ H)
{
    int b   = blockIdx.y;
    int idx = blockIdx.x * 256 + threadIdx.x;
    int y   = idx >> 9;
    int xx  = idx & 511;

    const float* xb = x + (size_t)b * 3 * 262144;
    float r  = xb[idx];
    float g  = xb[262144 + idx];
    float bl = xb[2 * 262144 + idx];

    float Y =  0.299f * r + 0.587f * g + 0.114f * bl;
    float U = -0.147f * r - 0.289f * g + 0.436f * bl;
    float V =  0.615f * r - 0.515f * g - 0.100f * bl;

    float* dst = (y & 1) ? H : L;
    size_t o = (size_t)(y >> 1) * 512 + xx;
    const size_t istr = (size_t)256 * 512;
    dst[(size_t)(0 * 8 + b) * istr + o] = Y;
    dst[(size_t)(1 * 8 + b) * istr + o] = U;
    dst[(size_t)(2 * 8 + b) * istr + o] = V;
}

// ---------------------------------------------------------------------------
// Stage-1 helper: conv 1->8 (pairs 4g..4g+3) + relu for a 2x2 quad of hidden
// positions per thread. Tap rows hy..hy+3 shared between the two output rows:
// 8 LDS.128 per 4 positions (was 12). CHK=false for interior blocks.
// ---------------------------------------------------------------------------
template <bool CHK>
__device__ __forceinline__ void stage1(const float2* sIn, char* sHb,
                                       int pset, int g, int by, int bx,
                                       int h, int w, int tid)
{
    // 33 row-pairs x 17 col-pairs (hidden grid 66 x 34)
    for (int idx = tid; idx < 33 * 17; idx += 256) {
        int hyp = idx / 17, hp = idx - hyp * 17;
        int hy = hyp * 2, hx = hp * 2;

        ull A[4], B[4], C[4], D[4];   // [pair] for pos (r0,c0)(r0,c1)(r1,c0)(r1,c1)
#pragma unroll
        for (int p = 0; p < 4; p++) {
            ull bb = c_pack.b1[pset][4 * g + p];
            A[p] = bb; B[p] = bb; C[p] = bb; D[p] = bb;
        }

#pragma unroll
        for (int dy = 0; dy < 4; dy++) {
            const ull* row = (const ull*)&sIn[(hy + dy) * 36 + hx];
            ulonglong2 ta = *(const ulonglong2*)row;        // taps hx, hx+1
            ulonglong2 tb = *(const ulonglong2*)(row + 2);  // taps hx+2, hx+3
            ull t0 = ta.x, t1 = ta.y, t2 = tb.x, t3 = tb.y;

            if (dy < 3) {       // contributes to output row hy (kernel row dy)
#pragma unroll
                for (int p = 0; p < 4; p++) {
                    ull w0 = c_pack.w1[pset][4 * g + p][dy * 3 + 0];
                    ull w1 = c_pack.w1[pset][4 * g + p][dy * 3 + 1];
                    ull w2 = c_pack.w1[pset][4 * g + p][dy * 3 + 2];
                    A[p] = fma2(w0, t0, A[p]); B[p] = fma2(w0, t1, B[p]);
                    A[p] = fma2(w1, t1, A[p]); B[p] = fma2(w1, t2, B[p]);
                    A[p] = fma2(w2, t2, A[p]); B[p] = fma2(w2, t3, B[p]);
                }
            }
            if (dy >= 1) {      // contributes to row hy+1 (kernel row dy-1)
#pragma unroll
                for (int p = 0; p < 4; p++) {
                    ull w0 = c_pack.w1[pset][4 * g + p][(dy - 1) * 3 + 0];
                    ull w1 = c_pack.w1[pset][4 * g + p][(dy - 1) * 3 + 1];
                    ull w2 = c_pack.w1[pset][4 * g + p][(dy - 1) * 3 + 2];
                    C[p] = fma2(w0, t0, C[p]); D[p] = fma2(w0, t1, D[p]);
                    C[p] = fma2(w1, t1, C[p]); D[p] = fma2(w1, t2, D[p]);
                    C[p] = fma2(w2, t2, C[p]); D[p] = fma2(w2, t3, D[p]);
                }
            }
        }

        bool vA = true, vB = true, vC = true, vD = true;
        if (CHK) {
            int gy = by + hy - 1, gx = bx + hx - 1;
            bool vy0 = (gy >= 0 && gy < h), vy1 = (gy + 1 >= 0 && gy + 1 < h);
            bool vx0 = (gx >= 0 && gx < w), vx1 = (gx + 1 >= 0 && gx + 1 < w);
            vA = vy0 && vx0; vB = vy0 && vx1;
            vC = vy1 && vx0; vD = vy1 && vx1;
        }

        unsigned b00 = (unsigned)(hy * 36 + hx) * 32;
        unsigned a00 = swz(b00);
        unsigned a01 = swz(b00 + 32);
        unsigned a10 = swz(b00 + 36 * 32);
        unsigned a11 = swz(b00 + 36 * 32 + 32);

        // store one quad position: pairs 0,1 then pairs 2,3 (offset ^16)
        {
            float2 f0 = unpack2(A[0]), f1 = unpack2(A[1]),
                   f2 = unpack2(A[2]), f3 = unpack2(A[3]);
            float4 v0 = make_float4(vA ? fmaxf(f0.x, 0.f) : 0.f,
                                    vA ? fmaxf(f0.y, 0.f) : 0.f,
                                    vA ? fmaxf(f1.x, 0.f) : 0.f,
                                    vA ? fmaxf(f1.y, 0.f) : 0.f);
            float4 v1 = make_float4(vA ? fmaxf(f2.x, 0.f) : 0.f,
                                    vA ? fmaxf(f2.y, 0.f) : 0.f,
                                    vA ? fmaxf(f3.x, 0.f) : 0.f,
                                    vA ? fmaxf(f3.y, 0.f) : 0.f);
            *(float4*)(sHb + a00)        = v0;
            *(float4*)(sHb + (a00 ^ 16)) = v1;
        }
        {
            float2 f0 = unpack2(B[0]), f1 = unpack2(B[1]),
                   f2 = unpack2(B[2]), f3 = unpack2(B[3]);
            float4 v0 = make_float4(vB ? fmaxf(f0.x, 0.f) : 0.f,
                                    vB ? fmaxf(f0.y, 0.f) : 0.f,
                                    vB ? fmaxf(f1.x, 0.f) : 0.f,
                                    vB ? fmaxf(f1.y, 0.f) : 0.f);
            float4 v1 = make_float4(vB ? fmaxf(f2.x, 0.f) : 0.f,
                                    vB ? fmaxf(f2.y, 0.f) : 0.f,
                                    vB ? fmaxf(f3.x, 0.f) : 0.f,
                                    vB ? fmaxf(f3.y, 0.f) : 0.f);
            *(float4*)(sHb + a01)        = v0;
            *(float4*)(sHb + (a01 ^ 16)) = v1;
        }
        {
            float2 f0 = unpack2(C[0]), f1 = unpack2(C[1]),
                   f2 = unpack2(C[2]), f3 = unpack2(C[3]);
            float4 v0 = make_float4(vC ? fmaxf(f0.x, 0.f) : 0.f,
                                    vC ? fmaxf(f0.y, 0.f) : 0.f,
                                    vC ? fmaxf(f1.x, 0.f) : 0.f,
                                    vC ? fmaxf(f1.y, 0.f) : 0.f);
            float4 v1 = make_float4(vC ? fmaxf(f2.x, 0.f) : 0.f,
                                    vC ? fmaxf(f2.y, 0.f) : 0.f,
                                    vC ? fmaxf(f3.x, 0.f) : 0.f,
                                    vC ? fmaxf(f3.y, 0.f) : 0.f);
            *(float4*)(sHb + a10)        = v0;
            *(float4*)(sHb + (a10 ^ 16)) = v1;
        }
        {
            float2 f0 = unpack2(D[0]), f1 = unpack2(D[1]),
                   f2 = unpack2(D[2]), f3 = unpack2(D[3]);
            float4 v0 = make_float4(vD ? fmaxf(f0.x, 0.f) : 0.f,
                                    vD ? fmaxf(f0.y, 0.f) : 0.f,
                                    vD ? fmaxf(f1.x, 0.f) : 0.f,
                                    vD ? fmaxf(f1.y, 0.f) : 0.f);
            float4 v1 = make_float4(vD ? fmaxf(f2.x, 0.f) : 0.f,
                                    vD ? fmaxf(f2.y, 0.f) : 0.f,
                                    vD ? fmaxf(f3.x, 0.f) : 0.f,
                                    vD ? fmaxf(f3.y, 0.f) : 0.f);
            *(float4*)(sHb + a11)        = v0;
            *(float4*)(sHb + (a11 ^ 16)) = v1;
        }
    }
}

// ---------------------------------------------------------------------------
// Kernel 2: fused subnet + lift.  O[p] = S[p] + sign*subnet(I)[p]
// Tile 32w x 64h, 256 threads, 2 passes of 8 channels (4 pairs, 32B/pos).
// grid.z in [0, 2*NIMG): z < NIMG uses buffer set A, else set B.
// SAME padding of conv2 zero-pads the *hidden* tensor (off-image hidden = 0).
// ---------------------------------------------------------------------------
__global__ void __launch_bounds__(288, 2)
subnet_lift_kernel(const float* __restrict__ IA, const float* __restrict__ SA,
                   float* __restrict__ OA,
                   const float* __restrict__ IB, const float* __restrict__ SB,
                   float* __restrict__ OB,
                   int pset, float sign, int h, int w)
{
    extern __shared__ char dynsmem[];
    char*   sHb = dynsmem;                          // 66*36 pos * 32B
    float2* sIn = (float2*)(dynsmem + SH_BYTES);    // 68 rows * 36 cols, dup'd

    const int tid = threadIdx.x;
    int z = blockIdx.z;
    const int setB = (z >= NIMG);
    const int img  = setB ? z - NIMG : z;
    const float* I = setB ? IB : IA;
    const float* S = setB ? SB : SA;
    float*       O = setB ? OB : OA;

    const int bx = blockIdx.x * 32;
    const int by = blockIdx.y * 64;
    const float* Ii = I + (size_t)img * h * w;

    const bool interior = (bx >= 2) && (bx + 34 <= w) &&
                          (by >= 2) && (by + 66 <= h);

    // --- load input tile (rows by-2..by+65, cols bx-2..bx+33), duplicated ---
    if (interior) {
        for (int idx = tid; idx < 68 * 36; idx += 256) {
            int ly = idx / 36, lx = idx - ly * 36;
            float v = Ii[(size_t)(by + ly - 2) * w + (bx + lx - 2)];
            sIn[idx] = make_float2(v, v);
        }
    } else {
        for (int idx = tid; idx < 68 * 36; idx += 256) {
            int ly = idx / 36, lx = idx - ly * 36;
            int gy = by + ly - 2, gx = bx + lx - 2;
            float v = 0.f;
            if (gy >= 0 && gy < h && gx >= 0 && gx < w)
                v = Ii[(size_t)gy * w + gx];
            sIn[idx] = make_float2(v, v);
        }
    }
    __syncthreads();

    // stage-2 ownership: rows 2r, 2r+1; cols oxq..oxq+3
    const int r   = tid >> 3;            // 0..31
    const int oxq = (tid & 7) * 4;       // 0,4,...,28

    const ull bias2 = pack2(c_pack.b2[pset], 0.f);  // bias once per px (lo)
    ull a00 = bias2, a01 = bias2, a02 = bias2, a03 = bias2;  // row 2r
    ull a10 = bias2, a11 = bias2, a12 = bias2, a13 = bias2;  // row 2r+1

#pragma unroll 1
    for (int g = 0; g < 2; g++) {
        if (interior)
            stage1<false>(sIn, sHb, pset, g, by, bx, h, w, tid);
        else
            stage1<true>(sIn, sHb, pset, g, by, bx, h, w, tid);
        __syncthreads();

        const ull* w0A = c_pack.w2[pset][4 * g + 0];
        const ull* w0B = w0A + 9;
        const ull* w1A = c_pack.w2[pset][4 * g + 2];
        const ull* w1B = w1A + 9;

        // --- stage 2 partial: conv 8->1, 2 output rows sharing hidden rows.
        //     All 12 position-loads batched before the FMA block (latency). ---
#pragma unroll
        for (int hr = 0; hr < 4; hr++) {
            const int hy = 2 * r + hr;
            unsigned base = (unsigned)(hy * 36 + oxq) * 32;

            ull A0[6], B0[6], A1[6], B1[6];
#pragma unroll
            for (int j = 0; j < 6; j++) {
                unsigned a = swz(base + j * 32);
                ulonglong2 v0 = *(const ulonglong2*)(sHb + a);
                ulonglong2 v1 = *(const ulonglong2*)(sHb + (a ^ 16));
                A0[j] = v0.x; B0[j] = v0.y;
                A1[j] = v1.x; B1[j] = v1.y;
            }

            if (hr <= 2) {            // contributes to row 2r (dy = hr)
#pragma unroll
                for (int t = 0; t < 3; t++) {
                    ull wa = w0A[hr * 3 + t], wb = w0B[hr * 3 + t];
                    a00 = fma2(wa, A0[t],     a00);
                    a01 = fma2(wa, A0[t + 1], a01);
                    a02 = fma2(wa, A0[t + 2], a02);
                    a03 = fma2(wa, A0[t + 3], a03);
                    a00 = fma2(wb, B0[t],     a00);
                    a01 = fma2(wb, B0[t + 1], a01);
                    a02 = fma2(wb, B0[t + 2], a02);
                    a03 = fma2(wb, B0[t + 3], a03);
                    ull wc = w1A[hr * 3 + t], wd = w1B[hr * 3 + t];
                    a00 = fma2(wc, A1[t],     a00);
                    a01 = fma2(wc, A1[t + 1], a01);
                    a02 = fma2(wc, A1[t + 2], a02);
                    a03 = fma2(wc, A1[t + 3], a03);
                    a00 = fma2(wd, B1[t],     a00);
                    a01 = fma2(wd, B1[t + 1], a01);
                    a02 = fma2(wd, B1[t + 2], a02);
                    a03 = fma2(wd, B1[t + 3], a03);
                }
            }
            if (hr >= 1) {            // contributes to row 2r+1 (dy = hr-1)
#pragma unroll
                for (int t = 0; t < 3; t++) {
                    ull wa = w0A[(hr - 1) * 3 + t], wb = w0B[(hr - 1) * 3 + t];
                    a10 = fma2(wa, A0[t],     a10);
                    a11 = fma2(wa, A0[t + 1], a11);
                    a12 = fma2(wa, A0[t + 2], a12);
                    a13 = fma2(wa, A0[t + 3], a13);
                    a10 = fma2(wb, B0[t],     a10);
                    a11 = fma2(wb, B0[t + 1], a11);
                    a12 = fma2(wb, B0[t + 2], a12);
                    a13 = fma2(wb, B0[t + 3], a13);
                    ull wc = w1A[(hr - 1) * 3 + t], wd = w1B[(hr - 1) * 3 + t];
                    a10 = fma2(wc, A1[t],     a10);
                    a11 = fma2(wc, A1[t + 1], a11);
                    a12 = fma2(wc, A1[t + 2], a12);
                    a13 = fma2(wc, A1[t + 3], a13);
                    a10 = fma2(wd, B1[t],     a10);
                    a11 = fma2(wd, B1[t + 1], a11);
                    a12 = fma2(wd, B1[t + 2], a12);
                    a13 = fma2(wd, B1[t + 3], a13);
                }
            }
        }
        if (g == 0) __syncthreads();   // before next pass overwrites sH
    }

    // --- epilogue: O = S + sign*acc, float4 per row ---
    float2 f00 = unpack2(a00), f01 = unpack2(a01),
           f02 = unpack2(a02), f03 = unpack2(a03);
    float2 f10 = unpack2(a10), f11 = unpack2(a11),
           f12 = unpack2(a12), f13 = unpack2(a13);

    const float* Si = S + (size_t)img * h * w;
    float* Oi = O + (size_t)img * h * w;
    size_t p0 = (size_t)(by + 2 * r) * w + bx + oxq;
    size_t p1 = p0 + w;

    float4 s0 = *(const float4*)(Si + p0);
    float4 s1 = *(const float4*)(Si + p1);
    float4 o0, o1;
    o0.x = s0.x + sign * (f00.x + f00.y);
    o0.y = s0.y + sign * (f01.x + f01.y);
    o0.z = s0.z + sign * (f02.x + f02.y);
    o0.w = s0.w + sign * (f03.x + f03.y);
    o1.x = s1.x + sign * (f10.x + f10.y);
    o1.y = s1.y + sign * (f11.x + f11.y);
    o1.z = s1.z + sign * (f12.x + f12.y);
    o1.w = s1.w + sign * (f13.x + f13.y);
    *(float4*)(Oi + p0) = o0;
    *(float4*)(Oi + p1) = o1;
}

// ---------------------------------------------------------------------------
// Kernel 3: transpose + even/odd split (L and H via grid.z).
// ---------------------------------------------------------------------------
__global__ void transpose_split_kernel(const float* __restrict__ Lsrc,
                                       const float* __restrict__ Hsrc,
                                       float* __restrict__ LLd, float* __restrict__ HLd,
                                       float* __restrict__ LHd, float* __restrict__ HHd,
                                       int h, int w)
{
    __shared__ float tile[32][65];
    int z = blockIdx.z;
    int which = z / NIMG, img = z - which * NIMG;
    const float* T = which ? Hsrc : Lsrc;
    float* E = which ? LHd : LLd;
    float* O = which ? HHd : HLd;

    const int c0 = blockIdx.x * 32;
    const int r0 = blockIdx.y * 32;
    const int tx = threadIdx.x, ty = threadIdx.y;

    const float* Ti = T + (size_t)img * h * w;
#pragma unroll
    for (int k = 0; k < 4; k++) {
        int cc = ty + 8 * k;
        const float* row = Ti + (size_t)(c0 + cc) * w + 2 * r0;
        tile[cc][tx]      = row[tx];
        tile[cc][tx + 32] = row[tx + 32];
    }
    __syncthreads();

    size_t imgo = (size_t)img * (w / 2) * h;
#pragma unroll
    for (int k = 0; k < 4; k++) {
        int rr = ty + 8 * k;
        size_t o = imgo + (size_t)(r0 + rr) * h + c0 + tx;
        E[o] = tile[tx][2 * rr];
        O[o] = tile[tx][2 * rr + 1];
    }
}

// ---------------------------------------------------------------------------
// Kernel 4: gather. out[b, q*3+c, i, j] = Q_q[c*8+b, j, i]
// ---------------------------------------------------------------------------
__global__ void gather_kernel(const float* __restrict__ LL, const float* __restrict__ HL,
                              const float* __restrict__ LH, const float* __restrict__ HH,
                              float* __restrict__ out)
{
    __shared__ float tile[32][33];
    int z = blockIdx.z;
    int q = z / NIMG, img = z - q * NIMG;
    const float* Q = (q == 0) ? LL : (q == 1) ? HL : (q == 2) ? LH : HH;
    int b = img & 7, cch = img >> 3;
    int chan = q * 3 + cch;

    int i0 = blockIdx.x * 32, j0 = blockIdx.y * 32;
    int tx = threadIdx.x, ty = threadIdx.y;

    const float* Qi = Q + (size_t)img * 65536;
#pragma unroll
    for (int k = 0; k < 4; k++) {
        int jj = ty + 8 * k;
        tile[jj][tx] = Qi[(size_t)(j0 + jj) * 256 + i0 + tx];
    }
    __syncthreads();

    float* o = out + ((size_t)b * 12 + chan) * 65536;
#pragma unroll
    for (int k = 0; k < 4; k++) {
        int ii = ty + 8 * k;
        o[(size_t)(i0 + ii) * 256 + j0 + tx] = tile[tx][ii];
    }
}

// ---------------------------------------------------------------------------
extern "C" void kernel_launch(void* const* d_in, const int* in_sizes, int n_in,
                              void* d_out, int out_size)
{
    const float* x   = (const float*)d_in[0];
    const float* Wp1 = (const float*)d_in[1];
    const float* bp1 = (const float*)d_in[2];
    const float* Wp2 = (const float*)d_in[3];
    const float* bp2 = (const float*)d_in[4];
    const float* Wu1 = (const float*)d_in[5];
    const float* bu1 = (const float*)d_in[6];
    const float* Wu2 = (const float*)d_in[7];
    const float* bu2 = (const float*)d_in[8];
    float* out = (float*)d_out;

    // opt in to >48KB dynamic SMEM (idempotent)
    cudaFuncSetAttribute(subnet_lift_kernel,
                         cudaFuncAttributeMaxDynamicSharedMemorySize, SMEM_TOTAL);

    // pack weights on device, then stage into __constant__
    prep_kernel<<<1, 256>>>(Wp1, bp1, Wp2, bp2, Wu1, bu1, Wu2, bu2);
    PackedW* pg;
    cudaGetSymbolAddress((void**)&pg, g_pack);
    cudaMemcpyToSymbolAsync(c_pack, pg, sizeof(PackedW), 0, cudaMemcpyDeviceToDevice);

    float *pL, *pH, *pLL, *pHL, *pLH, *pHH;
    cudaGetSymbolAddress((void**)&pL,  g_L);
    cudaGetSymbolAddress((void**)&pH,  g_H);
    cudaGetSymbolAddress((void**)&pLL, g_LL);
    cudaGetSymbolAddress((void**)&pHL, g_HL);
    cudaGetSymbolAddress((void**)&pLH, g_LH);
    cudaGetSymbolAddress((void**)&pHH, g_HH);

    // 1) rgb->yuv + row split
    yuv_split_kernel<<<dim3(1024, 8), 256>>>(x, pL, pH);

    // 2) lift 1 (rows), 24 x 256 x 512 ; tiles 32w x 64h
    dim3 g1(512 / 32, 256 / 64, NIMG);
    subnet_lift_kernel<<<g1, 256, SMEM_TOTAL>>>(pL, pH, pH, pL, pH, pH,
                                                0, -1.f, 256, 512);
    subnet_lift_kernel<<<g1, 256, SMEM_TOTAL>>>(pH, pL, pL, pH, pL, pL,
                                                1, +1.f, 256, 512);

    // 3) transpose + column split
    dim3 gt(256 / 32, 256 / 32, 2 * NIMG);
    transpose_split_kernel<<<gt, dim3(32, 8)>>>(pL, pH, pLL, pHL, pLH, pHH, 256, 512);

    // 4) lift 2 (L branch) and lift 3 (H branch) fused per step, grid.z = 48
    dim3 g2(256 / 32, 256 / 64, 2 * NIMG);
    subnet_lift_kernel<<<g2, 256, SMEM_TOTAL>>>(pLL, pHL, pHL, pLH, pHH, pHH,
                                                0, -1.f, 256, 256);
    subnet_lift_kernel<<<g2, 256, SMEM_TOTAL>>>(pHL, pLL, pLL, pHH, pLH, pLH,
                                                1, +1.f, 256, 256);

    // 5) transpose back + batch2channel + concat -> out [8,12,256,256]
    gather_kernel<<<dim3(8, 8, 96), dim3(32, 8)>>>(pLL, pHL, pLH, pHH, out);
}